// round 4
// baseline (speedup 1.0000x reference)
#include <cuda_runtime.h>
#include <math.h>
#include <stdint.h>

#define B_   4096
#define J_   32
#define E_   256
#define ROWS (B_ * J_)

// ======================= scratch (device globals) ==========================
__device__ float g_c1[B_ * E_];     // bias + x @ W^T
__device__ float g_c2[J_ * E_];     // keys @ V^T
__device__ float g_xk[B_ * J_];     // x . key_j   (raw dot, pre-sigmoid)

// ======================= PTX helpers =======================================
__device__ __forceinline__ uint32_t smem_u32(const void* p) {
    uint32_t a;
    asm("{ .reg .u64 t; cvta.to.shared.u64 t, %1; cvt.u32.u64 %0, t; }"
        : "=r"(a) : "l"(p));
    return a;
}
__device__ __forceinline__ uint32_t tf32u(float x) {   // round-to-nearest tf32
    uint32_t r;
    asm("cvt.rna.tf32.f32 %0, %1;" : "=r"(r) : "f"(x));
    return r;
}

#define CP_ASYNC16(dst, src)                                                  \
    asm volatile("cp.async.cg.shared.global [%0], [%1], 16;"                  \
        :: "r"(dst), "l"(__cvta_generic_to_global((const void*)(src))) : "memory")
#define CP_COMMIT() asm volatile("cp.async.commit_group;" ::: "memory")
#define CP_WAIT0()  asm volatile("cp.async.wait_group 0;" ::: "memory")

__device__ __forceinline__ void mma_tf32(float* d, const uint32_t* a,
                                         const uint32_t* b) {
    asm volatile(
        "mma.sync.aligned.m16n8k8.row.col.f32.tf32.tf32.f32 "
        "{%0,%1,%2,%3}, {%4,%5,%6,%7}, {%8,%9}, {%0,%1,%2,%3};"
        : "+f"(d[0]), "+f"(d[1]), "+f"(d[2]), "+f"(d[3])
        : "r"(a[0]), "r"(a[1]), "r"(a[2]), "r"(a[3]), "r"(b[0]), "r"(b[1]));
}

// ======================= main kernel config ================================
// 512 thr (16 warps, 4m x 4n). CTA tile M=128, N=256, K=256 (8 chunks of 32).
// A: resident fp32 row-major pitch 260 (raw bits fed to tf32 mma).
// B: double-buffered, pre-converted tf32 in fragment-permuted blocks:
//    block (nb, kbl) of 8n x 8k, 66 words (264B incl. pad).
//    element (n,k): word = (nb*4+kbl)*66 + ((n&7)*4 + (k&3))*2 + ((k>>2)&1)
//    fragment read (per nt,ks): uint2 at blk*66 + lane*2  -> {b0, b1}.
#define PA    260
#define AF    33280                  // 128*260 floats
#define BSF   8448                   // 128 blocks * 66 words per stage
#define XF    (AF + 2 * BSF)         // 50176 : x tile (4 rows x 256)
#define GF    (XF + 1024)            // 51200 : gate[128]
#define REDF  (GF + 128)             // 51328 : red[128*4]
#define INVF  (REDF + 512)           // 51840 : inv[128]
#define SMEMF (INVF + 128)           // 51968 floats
#define MAIN_SMEM (SMEMF * 4)        // 207872 bytes

__global__ void __launch_bounds__(512, 1)
memcell_mma(const float* __restrict__ state, const float* __restrict__ U,
            const float* __restrict__ x, float* __restrict__ out)
{
    extern __shared__ float sm[];
    const int tid  = threadIdx.x;
    const int lane = tid & 31;
    const int wid  = tid >> 5;
    const int grp  = lane >> 2;
    const int tig  = lane & 3;
    const int mwarp = wid >> 2;       // 0..3 (32 rows each)
    const int nwarp = wid & 3;        // 0..3 (64 cols each)
    const int row0 = blockIdx.x * 128;
    const uint32_t sb = smem_u32(sm);

    // ---- stage A (state 128x256 fp32) via cp.async ----
    #pragma unroll
    for (int i = 0; i < 16; ++i) {
        int idx = tid + (i << 9);
        int r = idx >> 6, c4 = idx & 63;
        CP_ASYNC16(sb + (uint32_t)(r * PA + c4 * 4) * 4u,
                   state + (size_t)(row0 + r) * E_ + c4 * 4);
    }
    CP_COMMIT();

    // ---- LDG B chunk 0 ----
    float4 breg[4];
    #pragma unroll
    for (int i = 0; i < 4; ++i) {
        int idx = tid + (i << 9);
        int f = idx >> 3, k4 = idx & 7;
        breg[i] = reinterpret_cast<const float4*>(U + (size_t)f * E_)[k4];
    }

    // ---- x tile (4 rows) ----
    if (tid < 256)
        reinterpret_cast<float4*>(sm + XF)[tid] =
            reinterpret_cast<const float4*>(x + (size_t)(row0 >> 5) * E_)[tid];

    CP_WAIT0();

    // ---- STS B chunk 0 (cvt RNA + permute) ----
    #pragma unroll
    for (int i = 0; i < 4; ++i) {
        int idx = tid + (i << 9);
        int f = idx >> 3, k4 = idx & 7;
        uint32_t* bp = reinterpret_cast<uint32_t*>(sm + AF)
                     + ((f >> 3) * 4 + (k4 >> 1)) * 66 + (k4 & 1);
        const float* v = &breg[i].x;
        #pragma unroll
        for (int j = 0; j < 4; ++j)
            bp[((f & 7) * 4 + j) * 2] = tf32u(v[j]);
    }
    __syncthreads();

    // ---- fused gate: g[r] = sigmoid( x_b . s_r  +  xk[row] ) ----
    {
        int r = tid >> 2, q = tid & 3;
        const float* arow = sm + r * PA;
        const float* xrow = sm + XF + (r >> 5) * 256;
        float dot = 0.f;
        #pragma unroll
        for (int u = 0; u < 16; ++u) {
            int f4 = u * 4 + q;
            float4 av = *reinterpret_cast<const float4*>(arow + f4 * 4);
            float4 xv = *reinterpret_cast<const float4*>(xrow + f4 * 4);
            dot += av.x * xv.x + av.y * xv.y + av.z * xv.z + av.w * xv.w;
        }
        dot += __shfl_xor_sync(0xffffffffu, dot, 1);
        dot += __shfl_xor_sync(0xffffffffu, dot, 2);
        if (q == 0)
            sm[GF + r] = 1.f / (1.f + expf(-(dot + g_xk[row0 + r])));
    }

    float acc[2][8][4];
    #pragma unroll
    for (int mt = 0; mt < 2; ++mt)
        #pragma unroll
        for (int nt = 0; nt < 8; ++nt)
            #pragma unroll
            for (int q = 0; q < 4; ++q) acc[mt][nt][q] = 0.f;

    const int mbase = mwarp * 32;

    // ---- mainloop: 8 K-chunks of 32 ----
    #pragma unroll 1
    for (int c = 0; c < 8; ++c) {
        if (c + 1 < 8) {   // prefetch next B chunk into regs
            #pragma unroll
            for (int i = 0; i < 4; ++i) {
                int idx = tid + (i << 9);
                int f = idx >> 3, k4 = idx & 7;
                breg[i] = reinterpret_cast<const float4*>(
                              U + (size_t)f * E_ + (c + 1) * 32)[k4];
            }
        }

        const uint32_t* Bp = reinterpret_cast<const uint32_t*>(sm + AF)
                           + (c & 1) * BSF;
        #pragma unroll
        for (int ks = 0; ks < 4; ++ks) {
            uint32_t afr[2][4];
            #pragma unroll
            for (int mt = 0; mt < 2; ++mt) {
                const uint32_t* ap = reinterpret_cast<const uint32_t*>(
                    sm + (mbase + mt * 16 + grp) * PA + c * 32 + ks * 8 + tig);
                afr[mt][0] = ap[0];
                afr[mt][1] = ap[8 * PA];
                afr[mt][2] = ap[4];
                afr[mt][3] = ap[8 * PA + 4];
            }
            #pragma unroll
            for (int nt = 0; nt < 8; ++nt) {
                int nb = nwarp * 8 + nt;
                uint2 bv = *reinterpret_cast<const uint2*>(
                    Bp + (nb * 4 + ks) * 66 + lane * 2);
                uint32_t bfr[2] = {bv.x, bv.y};
                mma_tf32(acc[0][nt], afr[0], bfr);
                mma_tf32(acc[1][nt], afr[1], bfr);
            }
        }
        __syncthreads();
        if (c + 1 < 8) {
            uint32_t* Bn = reinterpret_cast<uint32_t*>(sm + AF)
                         + ((c + 1) & 1) * BSF;
            #pragma unroll
            for (int i = 0; i < 4; ++i) {
                int idx = tid + (i << 9);
                int f = idx >> 3, k4 = idx & 7;
                uint32_t* bp = Bn + ((f >> 3) * 4 + (k4 >> 1)) * 66 + (k4 & 1);
                const float* v = &breg[i].x;
                #pragma unroll
                for (int j = 0; j < 4; ++j)
                    bp[((f & 7) * 4 + j) * 2] = tf32u(v[j]);
            }
            __syncthreads();
        }
    }

    // ---- epilogue pass 1: v = s + g*relu(acc + c1 + c2); ss per row ----
    float* red = sm + REDF;
    float* inv = sm + INVF;
    #pragma unroll
    for (int mt = 0; mt < 2; ++mt) {
        #pragma unroll
        for (int r2 = 0; r2 < 2; ++r2) {
            int rl   = mbase + mt * 16 + grp + r2 * 8;
            int grow = row0 + rl;
            float gv = sm[GF + rl];
            const float* c1r = g_c1 + (size_t)(grow >> 5) * E_;
            const float* c2r = g_c2 + (size_t)(rl & 31) * E_;
            float ss = 0.f;
            #pragma unroll
            for (int nt = 0; nt < 8; ++nt) {
                int col = nwarp * 64 + nt * 8 + tig * 2;
                float2 sv  = *reinterpret_cast<float2*>(sm + rl * PA + col);
                float2 c1v = *reinterpret_cast<const float2*>(c1r + col);
                float2 c2v = *reinterpret_cast<const float2*>(c2r + col);
                float d0 = acc[mt][nt][r2 * 2 + 0] + c1v.x + c2v.x;
                float d1 = acc[mt][nt][r2 * 2 + 1] + c1v.y + c2v.y;
                float v0 = sv.x + gv * fmaxf(d0, 0.f);
                float v1 = sv.y + gv * fmaxf(d1, 0.f);
                ss += v0 * v0 + v1 * v1;
                *reinterpret_cast<float2*>(sm + rl * PA + col) = make_float2(v0, v1);
            }
            ss += __shfl_xor_sync(0xffffffffu, ss, 1);
            ss += __shfl_xor_sync(0xffffffffu, ss, 2);
            if (tig == 0) red[rl * 4 + nwarp] = ss;
        }
    }
    __syncthreads();
    if (tid < 128) {
        float s = red[tid * 4] + red[tid * 4 + 1]
                + red[tid * 4 + 2] + red[tid * 4 + 3];
        inv[tid] = 1.f / (sqrtf(s) + 1e-8f);
    }
    __syncthreads();

    // ---- epilogue pass 2: coalesced normalized writeback ----
    #pragma unroll
    for (int i = 0; i < 16; ++i) {
        int idx = tid + (i << 9);
        int r = idx >> 6, c4 = idx & 63;
        float iv = inv[r];
        float4 v = *reinterpret_cast<float4*>(sm + r * PA + c4 * 4);
        v.x *= iv; v.y *= iv; v.z *= iv; v.w *= iv;
        reinterpret_cast<float4*>(out + (size_t)(row0 + r) * E_)[c4] = v;
    }
}

// ======================= side kernels ======================================
#define TILE 64
#define KC   32
#define UPITCH 260
#define S_FLOATS   (TILE * E_)
#define U_FLOATS   (KC * UPITCH)
#define C1_SMEM    ((S_FLOATS + U_FLOATS) * 4)

__device__ __forceinline__ void load_a_tile(const float* __restrict__ A,
                                            int row0, float4* s4, int tid)
{
    #pragma unroll
    for (int it = 0; it < (TILE * E_ / 4) / 256; ++it) {
        int idx = tid + 256 * it;
        int r   = idx >> 6;
        int f4  = idx & 63;
        float4 vv = reinterpret_cast<const float4*>(A)[(size_t)(row0 + r) * (E_ / 4) + f4];
        s4[(r << 6) + (f4 ^ ((r >> 3) & 7))] = vv;
    }
}

__device__ __forceinline__ void load_u_chunk(const float* __restrict__ Wm,
                                             int kc0, float* u_sm, int tid)
{
    #pragma unroll
    for (int it = 0; it < (E_ * KC / 4) / 256; ++it) {
        int idx = tid + 256 * it;
        int f   = idx >> 3;
        int k4  = idx & 7;
        float4 vv = reinterpret_cast<const float4*>(Wm)[(size_t)f * (E_ / 4) + (kc0 >> 2) + k4];
        int kb = k4 * 4;
        u_sm[(kb + 0) * UPITCH + f] = vv.x;
        u_sm[(kb + 1) * UPITCH + f] = vv.y;
        u_sm[(kb + 2) * UPITCH + f] = vv.z;
        u_sm[(kb + 3) * UPITCH + f] = vv.w;
    }
}

__device__ __forceinline__ void mm_chunk(const float4* s4, const float* u_sm,
                                         int kc0, int rg, int cg, float acc[8][8])
{
    #pragma unroll 2
    for (int k0 = 0; k0 < KC; k0 += 4) {
        float4 a[8];
        int f4 = ((kc0 + k0) >> 2) ^ rg;
        #pragma unroll
        for (int i = 0; i < 8; ++i)
            a[i] = s4[((rg * 8 + i) << 6) + f4];
        #pragma unroll
        for (int kk = 0; kk < 4; ++kk) {
            const float* up = u_sm + (k0 + kk) * UPITCH + cg * 8;
            float4 b0 = *reinterpret_cast<const float4*>(up);
            float4 b1 = *reinterpret_cast<const float4*>(up + 4);
            #pragma unroll
            for (int i = 0; i < 8; ++i) {
                float av = (kk == 0) ? a[i].x : (kk == 1) ? a[i].y
                         : (kk == 2) ? a[i].z : a[i].w;
                acc[i][0] += av * b0.x;  acc[i][1] += av * b0.y;
                acc[i][2] += av * b0.z;  acc[i][3] += av * b0.w;
                acc[i][4] += av * b1.x;  acc[i][5] += av * b1.y;
                acc[i][6] += av * b1.z;  acc[i][7] += av * b1.w;
            }
        }
    }
}

__global__ void gemm_c2(const float* __restrict__ keys, const float* __restrict__ V)
{
    __shared__ float ks[E_];
    int j = blockIdx.x;
    int f = threadIdx.x;
    ks[f] = keys[j * E_ + f];
    __syncthreads();
    const float4* vp = reinterpret_cast<const float4*>(V) + (size_t)f * (E_ / 4);
    const float4* kp = reinterpret_cast<const float4*>(ks);
    float a = 0.f;
    #pragma unroll
    for (int e4 = 0; e4 < E_ / 4; ++e4) {
        float4 vv = vp[e4], k = kp[e4];
        a += vv.x * k.x + vv.y * k.y + vv.z * k.z + vv.w * k.w;
    }
    g_c2[j * E_ + f] = a;
}

__global__ void __launch_bounds__(256) gemm_c1(const float* __restrict__ x,
                                               const float* __restrict__ W,
                                               const float* __restrict__ bias)
{
    extern __shared__ float sh[];
    float4* s4  = reinterpret_cast<float4*>(sh);
    float* u_sm = sh + S_FLOATS;

    int tid = threadIdx.x;
    int rg = tid & 7, cg = tid >> 3;
    int row0 = blockIdx.x * TILE;

    load_a_tile(x, row0, s4, tid);

    float acc[8][8];
    #pragma unroll
    for (int i = 0; i < 8; ++i)
        #pragma unroll
        for (int jq = 0; jq < 8; ++jq) acc[i][jq] = 0.f;

    for (int c = 0; c < E_ / KC; ++c) {
        __syncthreads();
        load_u_chunk(W, c * KC, u_sm, tid);
        __syncthreads();
        mm_chunk(s4, u_sm, c * KC, rg, cg, acc);
    }

    int f0 = cg * 8;
    float bv[8];
    #pragma unroll
    for (int jq = 0; jq < 8; ++jq) bv[jq] = bias[f0 + jq];
    #pragma unroll
    for (int i = 0; i < 8; ++i) {
        int row = row0 + rg * 8 + i;
        float4 o0 = make_float4(acc[i][0] + bv[0], acc[i][1] + bv[1],
                                acc[i][2] + bv[2], acc[i][3] + bv[3]);
        float4 o1 = make_float4(acc[i][4] + bv[4], acc[i][5] + bv[5],
                                acc[i][6] + bv[6], acc[i][7] + bv[7]);
        float4* op2 = reinterpret_cast<float4*>(g_c1 + (size_t)row * E_ + f0);
        op2[0] = o0; op2[1] = o1;
    }
}

// xk[b][j] = dot(x_b, key_j)   (raw, pre-sigmoid)
__global__ void __launch_bounds__(256) xk_kernel(const float* __restrict__ x,
                                                 const float* __restrict__ keys)
{
    __shared__ float4 xs[E_ / 4];
    int b = blockIdx.x, tid = threadIdx.x;
    if (tid < E_ / 4) xs[tid] = reinterpret_cast<const float4*>(x + (size_t)b * E_)[tid];
    __syncthreads();

    int warp = tid >> 5, lane = tid & 31;
    #pragma unroll
    for (int t = 0; t < 4; ++t) {
        int jj = warp + t * 8;
        const float4* kp = reinterpret_cast<const float4*>(keys + (size_t)jj * E_);
        float p = 0.f;
        #pragma unroll
        for (int q = 0; q < 2; ++q) {
            float4 k = kp[lane + 32 * q];
            float4 xv = xs[lane + 32 * q];
            p += xv.x * k.x + xv.y * k.y + xv.z * k.z + xv.w * k.w;
        }
        #pragma unroll
        for (int o = 16; o; o >>= 1) p += __shfl_xor_sync(0xffffffffu, p, o);
        if (lane == 0) g_xk[b * J_ + jj] = p;
    }
}

// ===========================================================================
extern "C" void kernel_launch(void* const* d_in, const int* in_sizes, int n_in,
                              void* d_out, int out_size)
{
    const float* x     = (const float*)d_in[0];
    const float* state = (const float*)d_in[1];
    const float* keys  = (const float*)d_in[2];
    const float* U     = (const float*)d_in[3];
    const float* V     = (const float*)d_in[4];
    const float* W     = (const float*)d_in[5];
    const float* bias  = (const float*)d_in[6];
    float* out = (float*)d_out;

    cudaFuncSetAttribute(gemm_c1,     cudaFuncAttributeMaxDynamicSharedMemorySize, C1_SMEM);
    cudaFuncSetAttribute(memcell_mma, cudaFuncAttributeMaxDynamicSharedMemorySize, MAIN_SMEM);

    gemm_c2<<<J_, E_>>>(keys, V);
    xk_kernel<<<B_, 256>>>(x, keys);
    gemm_c1<<<B_ / TILE, 256, C1_SMEM>>>(x, W, bias);
    memcell_mma<<<ROWS / 128, 512, MAIN_SMEM>>>(state, U, x, out);
}

// round 5
// speedup vs baseline: 1.1619x; 1.1619x over previous
#include <cuda_runtime.h>
#include <math.h>
#include <stdint.h>

#define B_   4096
#define J_   32
#define E_   256
#define ROWS (B_ * J_)

// ======================= scratch (device globals) ==========================
__device__ float g_c1[B_ * E_];     // bias + x @ W^T
__device__ float g_c2[J_ * E_];     // keys @ V^T
__device__ float g_xk[B_ * J_];     // x . key_j   (raw dot, pre-sigmoid)

// ======================= PTX helpers =======================================
__device__ __forceinline__ uint32_t smem_u32(const void* p) {
    uint32_t a;
    asm("{ .reg .u64 t; cvta.to.shared.u64 t, %1; cvt.u32.u64 %0, t; }"
        : "=r"(a) : "l"(p));
    return a;
}

#define CP_ASYNC16(dst, src)                                                  \
    asm volatile("cp.async.cg.shared.global [%0], [%1], 16;"                  \
        :: "r"(dst), "l"(__cvta_generic_to_global((const void*)(src))) : "memory")
#define CP_COMMIT() asm volatile("cp.async.commit_group;" ::: "memory")
#define CP_WAIT1()  asm volatile("cp.async.wait_group 1;" ::: "memory")
#define CP_WAIT0()  asm volatile("cp.async.wait_group 0;" ::: "memory")

__device__ __forceinline__ void mma_tf32(float* d, const uint32_t* a,
                                         const uint32_t* b) {
    asm volatile(
        "mma.sync.aligned.m16n8k8.row.col.f32.tf32.tf32.f32 "
        "{%0,%1,%2,%3}, {%4,%5,%6,%7}, {%8,%9}, {%0,%1,%2,%3};"
        : "+f"(d[0]), "+f"(d[1]), "+f"(d[2]), "+f"(d[3])
        : "r"(a[0]), "r"(a[1]), "r"(a[2]), "r"(a[3]), "r"(b[0]), "r"(b[1]));
}

// ======================= shared GEMM config ================================
// 256 thr (8 warps, 2m x 4n), warp tile 64x64. CTA tile M=128, N=256,
// K=256 in 8 chunks of 32. A resident (pitch 260, raw fp32 -> HW tf32
// truncation). B double-buffered raw fp32 via cp.async (pitch 36).
#define PA    260
#define PB    36
#define AF    33280                  // 128*260 floats; B stages follow
#define BSF   9216                   // 256*36 floats per stage
#define XF    (AF + 2 * BSF)         // 51712 : x tile (4x256) / bias
#define GF    (XF + 1024)            // 52736 : gate[128]
#define REDF  (GF + 128)             // 52864 : red[128*4]
#define INVF  (REDF + 512)           // 53376 : inv[128]
#define SMEMF (INVF + 128)           // 53504 floats
#define MAIN_SMEM (SMEMF * 4)        // 214016 bytes

// Stage the 128x256 A tile (rows of Ag starting at row0) via cp.async.
__device__ __forceinline__ void stage_a(const float* __restrict__ Ag,
                                        int row0, uint32_t sb, int tid)
{
    #pragma unroll
    for (int i = 0; i < 32; ++i) {
        int idx = tid + (i << 8);
        int r = idx >> 6, c4 = idx & 63;
        CP_ASYNC16(sb + (uint32_t)(r * PA + c4 * 4) * 4u,
                   Ag + (size_t)(row0 + r) * E_ + c4 * 4);
    }
}

// Mainloop: acc += A_tile @ Bg^T  (Bg is 256x256 row-major [n][k]).
// Caller must have issued A staging cp.asyncs (uncommitted); this function
// commits them together with B chunk 0.
__device__ __forceinline__ void tf32_mainloop(const float* __restrict__ Bg,
    const float* __restrict__ sm, uint32_t sb, int tid,
    int mwarp, int nwarp, int grp, int tig, float acc[4][8][4])
{
    #pragma unroll
    for (int i = 0; i < 8; ++i) {                       // B chunk 0
        int idx = tid + (i << 8);
        int f = idx >> 3, k4 = idx & 7;
        CP_ASYNC16(sb + (uint32_t)(AF + f * PB + k4 * 4) * 4u,
                   Bg + (size_t)f * E_ + k4 * 4);
    }
    CP_COMMIT();                                        // group0 = A (+extras) + B0

    #pragma unroll 1
    for (int c = 0; c < 8; ++c) {
        __syncthreads();
        if (c + 1 < 8) {
            uint32_t bst = sb + (uint32_t)(AF + ((c + 1) & 1) * BSF) * 4u;
            #pragma unroll
            for (int i = 0; i < 8; ++i) {
                int idx = tid + (i << 8);
                int f = idx >> 3, k4 = idx & 7;
                CP_ASYNC16(bst + (uint32_t)(f * PB + k4 * 4) * 4u,
                           Bg + (size_t)f * E_ + (c + 1) * 32 + k4 * 4);
            }
            CP_COMMIT();
            CP_WAIT1();
        } else {
            CP_WAIT0();
        }
        __syncthreads();

        const float* Bb = sm + AF + (c & 1) * BSF;
        #pragma unroll
        for (int ks = 0; ks < 4; ++ks) {
            const int kb = ks * 8 + tig;
            uint32_t afr[4][4];
            #pragma unroll
            for (int mt = 0; mt < 4; ++mt) {
                const uint32_t* ap = reinterpret_cast<const uint32_t*>(
                    sm + (mwarp * 64 + mt * 16 + grp) * PA + c * 32 + kb);
                afr[mt][0] = ap[0];
                afr[mt][1] = ap[8 * PA];
                afr[mt][2] = ap[4];
                afr[mt][3] = ap[8 * PA + 4];
            }
            #pragma unroll
            for (int nt = 0; nt < 8; ++nt) {
                const uint32_t* bp = reinterpret_cast<const uint32_t*>(
                    Bb + (nwarp * 64 + nt * 8 + grp) * PB + kb);
                uint32_t bfr[2] = {bp[0], bp[4]};
                #pragma unroll
                for (int mt = 0; mt < 4; ++mt)
                    mma_tf32(acc[mt][nt], afr[mt], bfr);
            }
        }
    }
}

// ======================= main fused kernel =================================
__global__ void __launch_bounds__(256, 1)
memcell_mma(const float* __restrict__ state, const float* __restrict__ U,
            const float* __restrict__ x, float* __restrict__ out)
{
    extern __shared__ float sm[];
    const int tid  = threadIdx.x;
    const int lane = tid & 31;
    const int wid  = tid >> 5;
    const int grp  = lane >> 2;
    const int tig  = lane & 3;
    const int mwarp = wid >> 2;       // 0..1
    const int nwarp = wid & 3;        // 0..3
    const int row0 = blockIdx.x * 128;
    const uint32_t sb = smem_u32(sm);

    // stage A (state) + x tile (4 rows x 256)
    stage_a(state, row0, sb, tid);
    CP_ASYNC16(sb + (uint32_t)(XF + tid * 4) * 4u,
               x + (size_t)(row0 >> 5) * E_ + tid * 4);

    float acc[4][8][4];
    #pragma unroll
    for (int mt = 0; mt < 4; ++mt)
        #pragma unroll
        for (int nt = 0; nt < 8; ++nt)
            #pragma unroll
            for (int q = 0; q < 4; ++q) acc[mt][nt][q] = 0.f;

    tf32_mainloop(U, sm, sb, tid, mwarp, nwarp, grp, tig, acc);

    // ---- fused gate from resident A tile: 2 threads per row ----
    {
        int r = tid >> 1, q = tid & 1;
        const float* arow = sm + r * PA;
        const float* xrow = sm + XF + (r >> 5) * 256;
        float dot = 0.f;
        #pragma unroll
        for (int u = 0; u < 32; ++u) {
            int f4 = u * 2 + q;
            float4 av = *reinterpret_cast<const float4*>(arow + f4 * 4);
            float4 xv = *reinterpret_cast<const float4*>(xrow + f4 * 4);
            dot += av.x * xv.x + av.y * xv.y + av.z * xv.z + av.w * xv.w;
        }
        dot += __shfl_xor_sync(0xffffffffu, dot, 1);
        if (q == 0)
            sm[GF + r] = 1.f / (1.f + expf(-(dot + g_xk[row0 + r])));
    }
    __syncthreads();

    // ---- epilogue pass 1: v = s + g*relu(acc + c1 + c2) -> A smem ----
    float* red = sm + REDF;
    float* inv = sm + INVF;
    #pragma unroll
    for (int mt = 0; mt < 4; ++mt) {
        #pragma unroll
        for (int r2 = 0; r2 < 2; ++r2) {
            int rl   = mwarp * 64 + mt * 16 + grp + r2 * 8;
            int grow = row0 + rl;
            float gv = sm[GF + rl];
            const float* c1r = g_c1 + (size_t)(grow >> 5) * E_;
            const float* c2r = g_c2 + (size_t)(rl & 31) * E_;
            float ss = 0.f;
            #pragma unroll
            for (int nt = 0; nt < 8; ++nt) {
                int col = nwarp * 64 + nt * 8 + tig * 2;
                float2 sv  = *reinterpret_cast<float2*>(sm + rl * PA + col);
                float2 c1v = *reinterpret_cast<const float2*>(c1r + col);
                float2 c2v = *reinterpret_cast<const float2*>(c2r + col);
                float d0 = acc[mt][nt][r2 * 2 + 0] + c1v.x + c2v.x;
                float d1 = acc[mt][nt][r2 * 2 + 1] + c1v.y + c2v.y;
                float v0 = sv.x + gv * fmaxf(d0, 0.f);
                float v1 = sv.y + gv * fmaxf(d1, 0.f);
                ss += v0 * v0 + v1 * v1;
                *reinterpret_cast<float2*>(sm + rl * PA + col) = make_float2(v0, v1);
            }
            ss += __shfl_xor_sync(0xffffffffu, ss, 1);
            ss += __shfl_xor_sync(0xffffffffu, ss, 2);
            if (tig == 0) red[rl * 4 + nwarp] = ss;
        }
    }
    __syncthreads();
    if (tid < 128) {
        float s = red[tid * 4] + red[tid * 4 + 1]
                + red[tid * 4 + 2] + red[tid * 4 + 3];
        inv[tid] = 1.f / (sqrtf(s) + 1e-8f);
    }
    __syncthreads();

    // ---- epilogue pass 2: coalesced normalized writeback ----
    #pragma unroll
    for (int i = 0; i < 32; ++i) {
        int idx = tid + (i << 8);
        int r = idx >> 6, c4 = idx & 63;
        float iv = inv[r];
        float4 v = *reinterpret_cast<float4*>(sm + r * PA + c4 * 4);
        v.x *= iv; v.y *= iv; v.z *= iv; v.w *= iv;
        reinterpret_cast<float4*>(out + (size_t)(row0 + r) * E_)[c4] = v;
    }
}

// ======================= c1 via the same MMA mainloop ======================
// g_c1[row][f] = bias[f] + sum_e x[row][e] * W[f][e]
__global__ void __launch_bounds__(256, 1)
c1_mma(const float* __restrict__ x, const float* __restrict__ W,
       const float* __restrict__ bias)
{
    extern __shared__ float sm[];
    const int tid  = threadIdx.x;
    const int lane = tid & 31;
    const int wid  = tid >> 5;
    const int grp  = lane >> 2;
    const int tig  = lane & 3;
    const int mwarp = wid >> 2;
    const int nwarp = wid & 3;
    const int row0 = blockIdx.x * 128;
    const uint32_t sb = smem_u32(sm);

    stage_a(x, row0, sb, tid);
    if (tid < 64)   // bias -> smem (256 floats)
        CP_ASYNC16(sb + (uint32_t)(XF + tid * 4) * 4u, bias + tid * 4);

    float acc[4][8][4];
    #pragma unroll
    for (int mt = 0; mt < 4; ++mt)
        #pragma unroll
        for (int nt = 0; nt < 8; ++nt)
            #pragma unroll
            for (int q = 0; q < 4; ++q) acc[mt][nt][q] = 0.f;

    tf32_mainloop(W, sm, sb, tid, mwarp, nwarp, grp, tig, acc);

    #pragma unroll
    for (int mt = 0; mt < 4; ++mt) {
        #pragma unroll
        for (int r2 = 0; r2 < 2; ++r2) {
            int rl  = mwarp * 64 + mt * 16 + grp + r2 * 8;
            int row = row0 + rl;
            #pragma unroll
            for (int nt = 0; nt < 8; ++nt) {
                int col = nwarp * 64 + nt * 8 + tig * 2;
                float2 bv = *reinterpret_cast<const float2*>(sm + XF + col);
                float2 o  = make_float2(acc[mt][nt][r2 * 2 + 0] + bv.x,
                                        acc[mt][nt][r2 * 2 + 1] + bv.y);
                *reinterpret_cast<float2*>(g_c1 + (size_t)row * E_ + col) = o;
            }
        }
    }
}

// ======================= tiny side kernels =================================
__global__ void gemm_c2(const float* __restrict__ keys, const float* __restrict__ V)
{
    __shared__ float ks[E_];
    int j = blockIdx.x;
    int f = threadIdx.x;
    ks[f] = keys[j * E_ + f];
    __syncthreads();
    const float4* vp = reinterpret_cast<const float4*>(V) + (size_t)f * (E_ / 4);
    const float4* kp = reinterpret_cast<const float4*>(ks);
    float a = 0.f;
    #pragma unroll
    for (int e4 = 0; e4 < E_ / 4; ++e4) {
        float4 vv = vp[e4], k = kp[e4];
        a += vv.x * k.x + vv.y * k.y + vv.z * k.z + vv.w * k.w;
    }
    g_c2[j * E_ + f] = a;
}

// xk[b][j] = dot(x_b, key_j)
__global__ void __launch_bounds__(256) xk_kernel(const float* __restrict__ x,
                                                 const float* __restrict__ keys)
{
    __shared__ float4 xs[E_ / 4];
    int b = blockIdx.x, tid = threadIdx.x;
    if (tid < E_ / 4) xs[tid] = reinterpret_cast<const float4*>(x + (size_t)b * E_)[tid];
    __syncthreads();

    int warp = tid >> 5, lane = tid & 31;
    #pragma unroll
    for (int t = 0; t < 4; ++t) {
        int jj = warp + t * 8;
        const float4* kp = reinterpret_cast<const float4*>(keys + (size_t)jj * E_);
        float p = 0.f;
        #pragma unroll
        for (int q = 0; q < 2; ++q) {
            float4 k = kp[lane + 32 * q];
            float4 xv = xs[lane + 32 * q];
            p += xv.x * k.x + xv.y * k.y + xv.z * k.z + xv.w * k.w;
        }
        #pragma unroll
        for (int o = 16; o; o >>= 1) p += __shfl_xor_sync(0xffffffffu, p, o);
        if (lane == 0) g_xk[b * J_ + jj] = p;
    }
}

// ===========================================================================
extern "C" void kernel_launch(void* const* d_in, const int* in_sizes, int n_in,
                              void* d_out, int out_size)
{
    const float* x     = (const float*)d_in[0];
    const float* state = (const float*)d_in[1];
    const float* keys  = (const float*)d_in[2];
    const float* U     = (const float*)d_in[3];
    const float* V     = (const float*)d_in[4];
    const float* W     = (const float*)d_in[5];
    const float* bias  = (const float*)d_in[6];
    float* out = (float*)d_out;

    cudaFuncSetAttribute(c1_mma,      cudaFuncAttributeMaxDynamicSharedMemorySize, MAIN_SMEM);
    cudaFuncSetAttribute(memcell_mma, cudaFuncAttributeMaxDynamicSharedMemorySize, MAIN_SMEM);

    gemm_c2<<<J_, E_>>>(keys, V);
    xk_kernel<<<B_, 256>>>(x, keys);
    c1_mma<<<B_ / 128, 256, MAIN_SMEM>>>(x, W, bias);
    memcell_mma<<<ROWS / 128, 256, MAIN_SMEM>>>(state, U, x, out);
}